// round 12
// baseline (speedup 1.0000x reference)
#include <cuda_runtime.h>
#include <cuda_bf16.h>
#include <cstdint>

#define D 64
#define KNB 64
#define PADB 72    // bf16 smem row stride in shorts (144B): ldmatrix conflict-free

// ---------------- packed weights in global (prep once) ----------------
__device__ __align__(16) uint4 g_BW2[1024];   // GEMM B frags, lane-consecutive: [(nt*4+ks)*32 + l]
__device__ __align__(16) uint4 g_AW1hi[512];  // hs matvec A frags: [(mi*4+ks)*32+l]
__device__ __align__(16) uint4 g_AW1lo[512];
__device__ __align__(16) uint4 g_AW2hi[512];  // g matvec A frags (W2^T)
__device__ __align__(16) uint4 g_AW2lo[512];

#define MMA(ac, A, B0, B1) \
    asm volatile("mma.sync.aligned.m16n8k16.row.col.f32.bf16.bf16.f32 " \
        "{%0,%1,%2,%3}, {%4,%5,%6,%7}, {%8,%9}, {%0,%1,%2,%3};" \
        : "+f"((ac)[0]), "+f"((ac)[1]), "+f"((ac)[2]), "+f"((ac)[3]) \
        : "r"((A)[0]), "r"((A)[1]), "r"((A)[2]), "r"((A)[3]), "r"(B0), "r"(B1))

__device__ __forceinline__ uint32_t smem_u32(const void* p) {
    uint32_t a;
    asm("{ .reg .u64 t; cvta.to.shared.u64 t, %1; cvt.u32.u64 %0, t; }" : "=r"(a) : "l"(p));
    return a;
}
__device__ __forceinline__ void ldmat4(unsigned r[4], uint32_t addr) {
    asm volatile("ldmatrix.sync.aligned.m8n8.x4.shared.b16 {%0,%1,%2,%3}, [%4];"
        : "=r"(r[0]), "=r"(r[1]), "=r"(r[2]), "=r"(r[3]) : "r"(addr));
}
__device__ __forceinline__ void split2(float2 f, unsigned& hi, unsigned& lo) {
    unsigned u0 = __float_as_uint(f.x), u1 = __float_as_uint(f.y);
    hi = (u0 >> 16) | (u1 & 0xFFFF0000u);
    float l0 = f.x - __uint_as_float(u0 & 0xFFFF0000u);
    float l1 = f.y - __uint_as_float(u1 & 0xFFFF0000u);
    __nv_bfloat162 p = __floats2bfloat162_rn(l0, l1);
    lo = *reinterpret_cast<unsigned*>(&p);
}
__device__ __forceinline__ void split1(float f, unsigned short& hi, unsigned short& lo) {
    unsigned u = __float_as_uint(f);
    hi = (unsigned short)(u >> 16);
    float lf = f - __uint_as_float(u & 0xFFFF0000u);
    lo = __bfloat16_as_ushort(__float2bfloat16(lf));
}
__device__ __forceinline__ float2 bfrecon(unsigned h, unsigned lo) {
    float2 a = __bfloat1622float2(*reinterpret_cast<__nv_bfloat162*>(&h));
    float2 b = __bfloat1622float2(*reinterpret_cast<__nv_bfloat162*>(&lo));
    return make_float2(a.x + b.x, a.y + b.y);
}

// ---------------- prep kernel ----------------
__global__ void prep_kernel(const float* __restrict__ fc_w) {
    int idx = blockIdx.x * 256 + threadIdx.x;
    if (idx < 1024) {
        int nt = idx >> 7, ks = (idx >> 5) & 3, g = (idx >> 2) & 7, tg = idx & 3;
        int nn = nt * 8 + g;
        int c0 = ks * 16 + 2 * tg, c1 = c0 + 8;
        const float* Wn = fc_w + nn * 128 + 64;
        unsigned hx, lx, hy, ly;
        split2(make_float2(Wn[c0], Wn[c0 + 1]), hx, lx);
        split2(make_float2(Wn[c1], Wn[c1 + 1]), hy, ly);
        g_BW2[idx] = make_uint4(hx, hy, lx, ly);
    } else if (idx < 2048) {
        int j = idx - 1024;
        int which = j >> 9;
        int jj = j & 511;
        int mi = jj >> 7, ks = (jj >> 5) & 3, l = jj & 31;
        int g = l >> 2, tg = l & 3;
        int ra = mi * 16 + g, rb = ra + 8;
        int c0 = ks * 16 + 2 * tg, c1 = c0 + 8;
        float a00, a01, b00, b01, a10, a11, b10, b11;
        if (which == 0) {
            a00 = fc_w[ra * 128 + c0]; a01 = fc_w[ra * 128 + c0 + 1];
            b00 = fc_w[rb * 128 + c0]; b01 = fc_w[rb * 128 + c0 + 1];
            a10 = fc_w[ra * 128 + c1]; a11 = fc_w[ra * 128 + c1 + 1];
            b10 = fc_w[rb * 128 + c1]; b11 = fc_w[rb * 128 + c1 + 1];
        } else {
            a00 = fc_w[c0 * 128 + 64 + ra]; a01 = fc_w[(c0 + 1) * 128 + 64 + ra];
            b00 = fc_w[c0 * 128 + 64 + rb]; b01 = fc_w[(c0 + 1) * 128 + 64 + rb];
            a10 = fc_w[c1 * 128 + 64 + ra]; a11 = fc_w[(c1 + 1) * 128 + 64 + ra];
            b10 = fc_w[c1 * 128 + 64 + rb]; b11 = fc_w[(c1 + 1) * 128 + 64 + rb];
        }
        uint4 hi, lo;
        split2(make_float2(a00, a01), hi.x, lo.x);
        split2(make_float2(b00, b01), hi.y, lo.y);
        split2(make_float2(a10, a11), hi.z, lo.z);
        split2(make_float2(b10, b11), hi.w, lo.w);
        if (which == 0) { g_AW1hi[jj] = hi; g_AW1lo[jj] = lo; }
        else            { g_AW2hi[jj] = hi; g_AW2lo[jj] = lo; }
    }
}

// ---------------- main fused kernel: 128 threads, 4 warps ----------------
__global__ void __launch_bounds__(128, 5) kgat_kernel(
    const float* __restrict__ src_embs,
    const float* __restrict__ dst_embs,
    const float* __restrict__ rel_embs,
    const float* __restrict__ fc_b,
    const int*   __restrict__ mask,
    float* __restrict__ out)
{
    __shared__ __align__(16) unsigned short sDhi[D * PADB];
    __shared__ __align__(16) unsigned short sDlo[D * PADB];
    __shared__ __align__(16) unsigned short sRhi[D * PADB];
    __shared__ __align__(16) unsigned short sRlo[D * PADB];
    __shared__ __align__(4) unsigned short sSRChi[D], sSRClo[D];
    __shared__ __align__(4) unsigned short sHShi[D], sHSlo[D];
    __shared__ __align__(4) unsigned short sGhi[D], sGlo[D];
    __shared__ __align__(16) float ssrc[D], shs[D], sb[D];
    __shared__ float sc1[KNB], sc2[KNB], sr2[KNB];
    __shared__ float sdr[KNB], sdh[KNB], satt[KNB];
    __shared__ float sagg[4 * D];
    __shared__ int   smask[KNB];

    const int n = blockIdx.x;
    const int t = threadIdx.x;
    const int w = t >> 5, l = t & 31;
    const int g = l >> 2, tg = l & 3;

    const float* gdst = dst_embs + (size_t)n * (KNB * D);
    const float* grel = rel_embs + (size_t)n * (KNB * D);

    if (t < D) {
        float sv = src_embs[(size_t)n * D + t];
        ssrc[t] = sv;
        split1(sv, sSRChi[t], sSRClo[t]);
        sb[t] = fc_b[t];
        smask[t] = mask[(size_t)n * KNB + t];
    }

    // ---- prologue: split dst/rel into bf16 hi/lo smem ----
    {
        const float4* gd4 = (const float4*)gdst;
        const float4* gr4 = (const float4*)grel;
#pragma unroll
        for (int j = 0; j < 8; j++) {
            int i = t + 128 * j;
            int row = i >> 4, c4 = i & 15;
            float4 dv = gd4[i];
            unsigned h0, l0, h1, l1;
            split2(make_float2(dv.x, dv.y), h0, l0);
            split2(make_float2(dv.z, dv.w), h1, l1);
            *(uint2*)&sDhi[row * PADB + c4 * 4] = make_uint2(h0, h1);
            *(uint2*)&sDlo[row * PADB + c4 * 4] = make_uint2(l0, l1);
            float4 rv = gr4[i];
            split2(make_float2(rv.x, rv.y), h0, l0);
            split2(make_float2(rv.z, rv.w), h1, l1);
            *(uint2*)&sRhi[row * PADB + c4 * 4] = make_uint2(h0, h1);
            *(uint2*)&sRlo[row * PADB + c4 * 4] = make_uint2(l0, l1);
        }
    }
    __syncthreads();

    const uint32_t aDhi = smem_u32(sDhi), aDlo = smem_u32(sDlo);
    const uint32_t aRhi = smem_u32(sRhi), aRlo = smem_u32(sRlo);
    const int m0 = w * 16;
    const uint32_t lmrow = (uint32_t)(m0 + (l & 15)) * (PADB * 2) + (uint32_t)(l >> 4) * 16;

    // ============ GEMM: hd = dst @ W2^T; fused c1/c2/r2 epilogue ============
    {
        float acc[8][4];
#pragma unroll
        for (int i = 0; i < 8; i++)
#pragma unroll
            for (int j = 0; j < 4; j++) acc[i][j] = 0.f;

#pragma unroll
        for (int ks = 0; ks < 4; ks++) {
            unsigned Ahi[4], Alo[4];
            ldmat4(Ahi, aDhi + lmrow + ks * 32);
            ldmat4(Alo, aDlo + lmrow + ks * 32);
#pragma unroll
            for (int nt = 0; nt < 8; nt++) {
                uint4 Bc = g_BW2[((nt * 4 + ks) << 5) + l];
                MMA(acc[nt], Ahi, Bc.x, Bc.y);
                MMA(acc[nt], Alo, Bc.x, Bc.y);
                MMA(acc[nt], Ahi, Bc.z, Bc.w);
            }
        }
        // epilogue: rel fragments via ldmatrix; c1, c2, r2 together
        float c1p0 = 0.f, c1p1 = 0.f, c2p0 = 0.f, c2p1 = 0.f, r2p0 = 0.f, r2p1 = 0.f;
#pragma unroll
        for (int cc = 0; cc < 4; cc++) {
            unsigned Rh[4], Rl[4];
            ldmat4(Rh, aRhi + lmrow + cc * 32);
            ldmat4(Rl, aRlo + lmrow + cc * 32);
            float2 e00 = bfrecon(Rh[0], Rl[0]);
            float2 e01 = bfrecon(Rh[1], Rl[1]);
            float2 e10 = bfrecon(Rh[2], Rl[2]);
            float2 e11 = bfrecon(Rh[3], Rl[3]);
            const int n0 = 2 * cc, n1 = 2 * cc + 1;
            c1p0 += acc[n0][0] * e00.x + acc[n0][1] * e00.y + acc[n1][0] * e10.x + acc[n1][1] * e10.y;
            c1p1 += acc[n0][2] * e01.x + acc[n0][3] * e01.y + acc[n1][2] * e11.x + acc[n1][3] * e11.y;
            c2p0 += acc[n0][0] * acc[n0][0] + acc[n0][1] * acc[n0][1] + acc[n1][0] * acc[n1][0] + acc[n1][1] * acc[n1][1];
            c2p1 += acc[n0][2] * acc[n0][2] + acc[n0][3] * acc[n0][3] + acc[n1][2] * acc[n1][2] + acc[n1][3] * acc[n1][3];
            r2p0 += e00.x * e00.x + e00.y * e00.y + e10.x * e10.x + e10.y * e10.y;
            r2p1 += e01.x * e01.x + e01.y * e01.y + e11.x * e11.x + e11.y * e11.y;
        }
#pragma unroll
        for (int s = 1; s < 4; s <<= 1) {
            c1p0 += __shfl_xor_sync(0xffffffffu, c1p0, s);
            c1p1 += __shfl_xor_sync(0xffffffffu, c1p1, s);
            c2p0 += __shfl_xor_sync(0xffffffffu, c2p0, s);
            c2p1 += __shfl_xor_sync(0xffffffffu, c2p1, s);
            r2p0 += __shfl_xor_sync(0xffffffffu, r2p0, s);
            r2p1 += __shfl_xor_sync(0xffffffffu, r2p1, s);
        }
        if (tg == 0) {
            sc1[m0 + g] = c1p0; sc1[m0 + g + 8] = c1p1;
            sc2[m0 + g] = c2p0; sc2[m0 + g + 8] = c2p1;
            sr2[m0 + g] = r2p0; sr2[m0 + g + 8] = r2p1;
        }
    }
    __syncthreads();

    // ===================== two GAT layers =====================
    for (int layer = 0; layer < 2; layer++) {
        // ---- hs = W1 @ src + b via MMA (B = pre-split src) ----
        {
            float acc[4] = {0.f, 0.f, 0.f, 0.f};
#pragma unroll
            for (int ks = 0; ks < 4; ks++) {
                const int k0 = ks * 16;
                unsigned B0 = 0u, B1 = 0u;
                if (g == 0) {
                    B0 = *(const unsigned*)&sSRChi[k0 + 2 * tg];
                    B1 = *(const unsigned*)&sSRChi[k0 + 2 * tg + 8];
                } else if (g == 1) {
                    B0 = *(const unsigned*)&sSRClo[k0 + 2 * tg];
                    B1 = *(const unsigned*)&sSRClo[k0 + 2 * tg + 8];
                }
                uint4 Ah = g_AW1hi[(w * 4 + ks) * 32 + l];
                uint4 Al = g_AW1lo[(w * 4 + ks) * 32 + l];
                MMA(acc, ((unsigned*)&Ah), B0, B1);
                MMA(acc, ((unsigned*)&Al), B0, B1);
            }
            if (tg == 0) {
                float h0 = acc[0] + acc[1] + sb[m0 + g];
                float h1 = acc[2] + acc[3] + sb[m0 + g + 8];
                shs[m0 + g] = h0; shs[m0 + g + 8] = h1;
                split1(h0, sHShi[m0 + g], sHSlo[m0 + g]);
                split1(h1, sHShi[m0 + g + 8], sHSlo[m0 + g + 8]);
            }
        }
        __syncthreads();
        // ---- g = W2^T @ hs via MMA (B = pre-split hs) ----
        {
            float acc[4] = {0.f, 0.f, 0.f, 0.f};
#pragma unroll
            for (int ks = 0; ks < 4; ks++) {
                const int k0 = ks * 16;
                unsigned B0 = 0u, B1 = 0u;
                if (g == 0) {
                    B0 = *(const unsigned*)&sHShi[k0 + 2 * tg];
                    B1 = *(const unsigned*)&sHShi[k0 + 2 * tg + 8];
                } else if (g == 1) {
                    B0 = *(const unsigned*)&sHSlo[k0 + 2 * tg];
                    B1 = *(const unsigned*)&sHSlo[k0 + 2 * tg + 8];
                }
                uint4 Ah = g_AW2hi[(w * 4 + ks) * 32 + l];
                uint4 Al = g_AW2lo[(w * 4 + ks) * 32 + l];
                MMA(acc, ((unsigned*)&Ah), B0, B1);
                MMA(acc, ((unsigned*)&Al), B0, B1);
            }
            if (tg == 0) {
                float g0 = acc[0] + acc[1];
                float g1 = acc[2] + acc[3];
                split1(g0, sGhi[m0 + g], sGlo[m0 + g]);
                split1(g1, sGhi[m0 + g + 8], sGlo[m0 + g + 8]);
            }
        }
        __syncthreads();
        // ---- dots via MMA: B cols [hs_hi, hs_lo, g_hi, g_lo]; A = rel (dr), dst (dh) ----
        {
            const unsigned short* vp = (g == 0) ? sHShi : (g == 1) ? sHSlo
                                      : (g == 2) ? sGhi : sGlo;
            float accR[4] = {0.f, 0.f, 0.f, 0.f};
            float accD[4] = {0.f, 0.f, 0.f, 0.f};
#pragma unroll
            for (int ks = 0; ks < 4; ks++) {
                const int k0 = ks * 16;
                unsigned B0 = 0u, B1 = 0u;
                if (g < 4) {
                    B0 = *(const unsigned*)&vp[k0 + 2 * tg];
                    B1 = *(const unsigned*)&vp[k0 + 2 * tg + 8];
                }
                unsigned F[4];
                ldmat4(F, aRhi + lmrow + ks * 32);
                MMA(accR, F, B0, B1);
                ldmat4(F, aRlo + lmrow + ks * 32);
                MMA(accR, F, B0, B1);
                ldmat4(F, aDhi + lmrow + ks * 32);
                MMA(accD, F, B0, B1);
                ldmat4(F, aDlo + lmrow + ks * 32);
                MMA(accD, F, B0, B1);
            }
            if (tg == 0) { sdr[m0 + g] = accR[0] + accR[1]; sdr[m0 + g + 8] = accR[2] + accR[3]; }
            if (tg == 1) { sdh[m0 + g] = accD[0] + accD[1]; sdh[m0 + g + 8] = accD[2] + accD[3]; }
        }
        __syncthreads();
        // ---- logits + masked softmax (warp 0; s2 inline) ----
        if (t < 32) {
            float v = shs[t] * shs[t] + shs[t + 32] * shs[t + 32];
#pragma unroll
            for (int s = 16; s; s >>= 1) v += __shfl_xor_sync(0xffffffffu, v, s);
            const float s2 = v;
            float e[2];
#pragma unroll
            for (int h = 0; h < 2; h++) {
                int k = t + 32 * h;
                float num = sc1[k] + sdr[k];
                float hn2 = s2 + 2.0f * sdh[k] + sc2[k];
                float hn = sqrtf(fmaxf(hn2, 0.0f));
                float rn = sqrtf(sr2[k]);
                float den = fmaxf(hn, 1e-8f) * fmaxf(rn, 1e-8f);
                float ee = num / den;
                ee = (ee < 0.0f) ? 0.2f * ee : ee;
                e[h] = (smask[k] > 0) ? ee : -9e15f;
            }
            float m = fmaxf(e[0], e[1]);
#pragma unroll
            for (int s = 16; s; s >>= 1) m = fmaxf(m, __shfl_xor_sync(0xffffffffu, m, s));
            float x0 = __expf(e[0] - m), x1 = __expf(e[1] - m);
            float sum = x0 + x1;
#pragma unroll
            for (int s = 16; s; s >>= 1) sum += __shfl_xor_sync(0xffffffffu, sum, s);
            float inv = 1.0f / sum;
            satt[t] = x0 * inv; satt[t + 32] = x1 * inv;
        }
        __syncthreads();
        // ---- agg: lane covers col pair (2l, 2l+1), rows 16w..16w+15 from global ----
        {
            float a0 = 0.f, a1 = 0.f;
#pragma unroll
            for (int j = 0; j < 16; j++) {
                const int k = 16 * w + j;
                const float av = satt[k];
                float2 dd = *(const float2*)(gdst + k * 64 + 2 * l);
                a0 = fmaf(av, dd.x, a0);
                a1 = fmaf(av, dd.y, a1);
            }
            *(float2*)&sagg[w * 64 + 2 * l] = make_float2(a0, a1);
        }
        __syncthreads();
        if (t < D) {
            float o = (sagg[t] + sagg[64 + t]) + (sagg[128 + t] + sagg[192 + t]) + ssrc[t];
            if (layer == 0) {
                ssrc[t] = o;
                split1(o, sSRChi[t], sSRClo[t]);
            } else {
                out[(size_t)n * D + t] = o;
            }
        }
        __syncthreads();
    }
}

extern "C" void kernel_launch(void* const* d_in, const int* in_sizes, int n_in,
                              void* d_out, int out_size) {
    const float* src  = (const float*)d_in[0];
    const float* dst  = (const float*)d_in[1];
    const float* rel  = (const float*)d_in[2];
    const float* fcw  = (const float*)d_in[3];
    const float* fcb  = (const float*)d_in[4];
    const int*   mask = (const int*)d_in[5];
    (void)n_in;

    int N = in_sizes[0] / D;   // 50000
    float* outp = (float*)d_out;
    (void)out_size;

    prep_kernel<<<8, 256>>>(fcw);
    kgat_kernel<<<N, 128>>>(src, dst, rel, fcb, mask, outp);
}

// round 13
// speedup vs baseline: 1.2415x; 1.2415x over previous
#include <cuda_runtime.h>
#include <cuda_bf16.h>
#include <cstdint>

#define D 64
#define KNB 64
#define PADB 72    // bf16 smem row stride in shorts (144B): ldmatrix conflict-free

// ---------------- packed weights in global (prep once) ----------------
__device__ __align__(16) uint4 g_BW2[1024];   // GEMM B frags, lane-consecutive: [(nt*4+ks)*32 + l]
__device__ __align__(16) uint4 g_AW1hi[512];  // hs matvec A frags: [(mi*4+ks)*32+l]
__device__ __align__(16) uint4 g_AW1lo[512];
__device__ __align__(16) uint4 g_AW2hi[512];  // g matvec A frags (W2^T)
__device__ __align__(16) uint4 g_AW2lo[512];

#define MMA(ac, A, B0, B1) \
    asm volatile("mma.sync.aligned.m16n8k16.row.col.f32.bf16.bf16.f32 " \
        "{%0,%1,%2,%3}, {%4,%5,%6,%7}, {%8,%9}, {%0,%1,%2,%3};" \
        : "+f"((ac)[0]), "+f"((ac)[1]), "+f"((ac)[2]), "+f"((ac)[3]) \
        : "r"((A)[0]), "r"((A)[1]), "r"((A)[2]), "r"((A)[3]), "r"(B0), "r"(B1))

__device__ __forceinline__ uint32_t smem_u32(const void* p) {
    uint32_t a;
    asm("{ .reg .u64 t; cvta.to.shared.u64 t, %1; cvt.u32.u64 %0, t; }" : "=r"(a) : "l"(p));
    return a;
}
__device__ __forceinline__ void ldmat4(unsigned r[4], uint32_t addr) {
    asm volatile("ldmatrix.sync.aligned.m8n8.x4.shared.b16 {%0,%1,%2,%3}, [%4];"
        : "=r"(r[0]), "=r"(r[1]), "=r"(r[2]), "=r"(r[3]) : "r"(addr));
}
__device__ __forceinline__ void split2(float2 f, unsigned& hi, unsigned& lo) {
    unsigned u0 = __float_as_uint(f.x), u1 = __float_as_uint(f.y);
    hi = (u0 >> 16) | (u1 & 0xFFFF0000u);
    float l0 = f.x - __uint_as_float(u0 & 0xFFFF0000u);
    float l1 = f.y - __uint_as_float(u1 & 0xFFFF0000u);
    __nv_bfloat162 p = __floats2bfloat162_rn(l0, l1);
    lo = *reinterpret_cast<unsigned*>(&p);
}
__device__ __forceinline__ float2 bfrecon(unsigned h, unsigned lo) {
    float2 a = __bfloat1622float2(*reinterpret_cast<__nv_bfloat162*>(&h));
    float2 b = __bfloat1622float2(*reinterpret_cast<__nv_bfloat162*>(&lo));
    return make_float2(a.x + b.x, a.y + b.y);
}
__device__ __forceinline__ float dot4(const float4& a, const float4& b) {
    return a.x * b.x + a.y * b.y + a.z * b.z + a.w * b.w;
}

// ---------------- prep kernel (identical to R9) ----------------
__global__ void prep_kernel(const float* __restrict__ fc_w) {
    int idx = blockIdx.x * 256 + threadIdx.x;
    if (idx < 1024) {
        int nt = idx >> 7, ks = (idx >> 5) & 3, g = (idx >> 2) & 7, tg = idx & 3;
        int nn = nt * 8 + g;
        int c0 = ks * 16 + 2 * tg, c1 = c0 + 8;
        const float* Wn = fc_w + nn * 128 + 64;
        unsigned hx, lx, hy, ly;
        split2(make_float2(Wn[c0], Wn[c0 + 1]), hx, lx);
        split2(make_float2(Wn[c1], Wn[c1 + 1]), hy, ly);
        g_BW2[idx] = make_uint4(hx, hy, lx, ly);
    } else if (idx < 2048) {
        int j = idx - 1024;
        int which = j >> 9;
        int jj = j & 511;
        int mi = jj >> 7, ks = (jj >> 5) & 3, l = jj & 31;
        int g = l >> 2, tg = l & 3;
        int ra = mi * 16 + g, rb = ra + 8;
        int c0 = ks * 16 + 2 * tg, c1 = c0 + 8;
        float a00, a01, b00, b01, a10, a11, b10, b11;
        if (which == 0) {
            a00 = fc_w[ra * 128 + c0]; a01 = fc_w[ra * 128 + c0 + 1];
            b00 = fc_w[rb * 128 + c0]; b01 = fc_w[rb * 128 + c0 + 1];
            a10 = fc_w[ra * 128 + c1]; a11 = fc_w[ra * 128 + c1 + 1];
            b10 = fc_w[rb * 128 + c1]; b11 = fc_w[rb * 128 + c1 + 1];
        } else {
            a00 = fc_w[c0 * 128 + 64 + ra]; a01 = fc_w[(c0 + 1) * 128 + 64 + ra];
            b00 = fc_w[c0 * 128 + 64 + rb]; b01 = fc_w[(c0 + 1) * 128 + 64 + rb];
            a10 = fc_w[c1 * 128 + 64 + ra]; a11 = fc_w[(c1 + 1) * 128 + 64 + ra];
            b10 = fc_w[c1 * 128 + 64 + rb]; b11 = fc_w[(c1 + 1) * 128 + 64 + rb];
        }
        uint4 hi, lo;
        split2(make_float2(a00, a01), hi.x, lo.x);
        split2(make_float2(b00, b01), hi.y, lo.y);
        split2(make_float2(a10, a11), hi.z, lo.z);
        split2(make_float2(b10, b11), hi.w, lo.w);
        if (which == 0) { g_AW1hi[jj] = hi; g_AW1lo[jj] = lo; }
        else            { g_AW2hi[jj] = hi; g_AW2lo[jj] = lo; }
    }
}

// ---------------- main fused kernel: 128 threads, 4 warps ----------------
__global__ void __launch_bounds__(128, 5) kgat_kernel(
    const float* __restrict__ src_embs,
    const float* __restrict__ dst_embs,
    const float* __restrict__ rel_embs,
    const float* __restrict__ fc_b,
    const int*   __restrict__ mask,
    float* __restrict__ out)
{
    __shared__ __align__(16) unsigned short sDhi[D * PADB];
    __shared__ __align__(16) unsigned short sDlo[D * PADB];
    __shared__ __align__(16) unsigned short sRhi[D * PADB];
    __shared__ __align__(16) unsigned short sRlo[D * PADB];
    __shared__ __align__(16) float ssrc[D], shs[D], sg[D], sb[D];
    __shared__ float sc1[KNB], sc2[KNB], sr2[KNB];
    __shared__ float sdr[KNB], sdh[KNB], satt[KNB];
    __shared__ float sagg[4 * D];
    __shared__ int   smask[KNB];

    const int n = blockIdx.x;
    const int t = threadIdx.x;
    const int w = t >> 5, l = t & 31;
    const int g = l >> 2, tg = l & 3;

    const float* gdst = dst_embs + (size_t)n * (KNB * D);
    const float* grel = rel_embs + (size_t)n * (KNB * D);

    if (t < D) {
        ssrc[t] = src_embs[(size_t)n * D + t];
        sb[t] = fc_b[t];
        smask[t] = mask[(size_t)n * KNB + t];
    }

    // ---- prologue: split dst/rel into bf16 hi/lo smem; fold in r2 ----
    {
        const float4* gd4 = (const float4*)gdst;
        const float4* gr4 = (const float4*)grel;
#pragma unroll
        for (int j = 0; j < 8; j++) {
            int i = t + 128 * j;
            int row = i >> 4, c4 = i & 15;
            float4 dv = gd4[i];
            unsigned h0, l0, h1, l1;
            split2(make_float2(dv.x, dv.y), h0, l0);
            split2(make_float2(dv.z, dv.w), h1, l1);
            *(uint2*)&sDhi[row * PADB + c4 * 4] = make_uint2(h0, h1);
            *(uint2*)&sDlo[row * PADB + c4 * 4] = make_uint2(l0, l1);
            float4 rv = gr4[i];
            split2(make_float2(rv.x, rv.y), h0, l0);
            split2(make_float2(rv.z, rv.w), h1, l1);
            *(uint2*)&sRhi[row * PADB + c4 * 4] = make_uint2(h0, h1);
            *(uint2*)&sRlo[row * PADB + c4 * 4] = make_uint2(l0, l1);
            float r2p = dot4(rv, rv);
            r2p += __shfl_xor_sync(0xffffffffu, r2p, 1);
            r2p += __shfl_xor_sync(0xffffffffu, r2p, 2);
            r2p += __shfl_xor_sync(0xffffffffu, r2p, 4);
            r2p += __shfl_xor_sync(0xffffffffu, r2p, 8);
            if ((l & 15) == 0) sr2[row] = r2p;
        }
    }
    __syncthreads();

    const uint32_t aDhi = smem_u32(sDhi), aDlo = smem_u32(sDlo);
    const uint32_t aRhi = smem_u32(sRhi), aRlo = smem_u32(sRlo);
    const int m0 = w * 16;
    const uint32_t lmrow = (uint32_t)(m0 + (l & 15)) * (PADB * 2) + (uint32_t)(l >> 4) * 16;

    // ---- hs1 = W1 @ src + b via MMA (R9 matvec) ----
    {
        float acc[4] = {0.f, 0.f, 0.f, 0.f};
#pragma unroll
        for (int ks = 0; ks < 4; ks++) {
            const int k0 = ks * 16;
            float2 v0 = *(const float2*)&ssrc[k0 + 2 * tg];
            float2 v1 = *(const float2*)&ssrc[k0 + 2 * tg + 8];
            unsigned h0, lo0, h1, lo1;
            split2(v0, h0, lo0);
            split2(v1, h1, lo1);
            unsigned B0 = (g == 0) ? h0 : (g == 1) ? lo0 : 0u;
            unsigned B1 = (g == 0) ? h1 : (g == 1) ? lo1 : 0u;
            uint4 Ah = g_AW1hi[(w * 4 + ks) * 32 + l];
            uint4 Al = g_AW1lo[(w * 4 + ks) * 32 + l];
            MMA(acc, ((unsigned*)&Ah), B0, B1);
            MMA(acc, ((unsigned*)&Al), B0, B1);
        }
        if (tg == 0) {
            shs[m0 + g] = acc[0] + acc[1] + sb[m0 + g];
            shs[m0 + g + 8] = acc[2] + acc[3] + sb[m0 + g + 8];
        }
    }
    __syncthreads();

    // ============ GEMM: hd = dst @ W2^T; epilogue: c1, c2, dr1, dh1 ============
    {
        float acc[8][4];
#pragma unroll
        for (int i = 0; i < 8; i++)
#pragma unroll
            for (int j = 0; j < 4; j++) acc[i][j] = 0.f;

#pragma unroll
        for (int ks = 0; ks < 4; ks++) {
            unsigned Ahi[4], Alo[4];
            ldmat4(Ahi, aDhi + lmrow + ks * 32);
            ldmat4(Alo, aDlo + lmrow + ks * 32);
#pragma unroll
            for (int nt = 0; nt < 8; nt++) {
                uint4 Bc = g_BW2[((nt * 4 + ks) << 5) + l];
                MMA(acc[nt], Ahi, Bc.x, Bc.y);
                MMA(acc[nt], Alo, Bc.x, Bc.y);
                MMA(acc[nt], Ahi, Bc.z, Bc.w);
            }
        }
        float c1p0 = 0.f, c1p1 = 0.f, c2p0 = 0.f, c2p1 = 0.f;
        float drp0 = 0.f, drp1 = 0.f, dhp0 = 0.f, dhp1 = 0.f;
#pragma unroll
        for (int cc = 0; cc < 4; cc++) {
            unsigned Rh[4], Rl[4];
            ldmat4(Rh, aRhi + lmrow + cc * 32);
            ldmat4(Rl, aRlo + lmrow + cc * 32);
            float2 e00 = bfrecon(Rh[0], Rl[0]);   // row g,   nt0
            float2 e01 = bfrecon(Rh[1], Rl[1]);   // row g+8, nt0
            float2 e10 = bfrecon(Rh[2], Rl[2]);   // row g,   nt1
            float2 e11 = bfrecon(Rh[3], Rl[3]);   // row g+8, nt1
            const int n0 = 2 * cc, n1 = 2 * cc + 1;
            float2 hv0 = *(const float2*)&shs[n0 * 8 + 2 * tg];
            float2 hv1 = *(const float2*)&shs[n1 * 8 + 2 * tg];
            c1p0 += acc[n0][0] * e00.x + acc[n0][1] * e00.y + acc[n1][0] * e10.x + acc[n1][1] * e10.y;
            c1p1 += acc[n0][2] * e01.x + acc[n0][3] * e01.y + acc[n1][2] * e11.x + acc[n1][3] * e11.y;
            c2p0 += acc[n0][0] * acc[n0][0] + acc[n0][1] * acc[n0][1] + acc[n1][0] * acc[n1][0] + acc[n1][1] * acc[n1][1];
            c2p1 += acc[n0][2] * acc[n0][2] + acc[n0][3] * acc[n0][3] + acc[n1][2] * acc[n1][2] + acc[n1][3] * acc[n1][3];
            drp0 += e00.x * hv0.x + e00.y * hv0.y + e10.x * hv1.x + e10.y * hv1.y;
            drp1 += e01.x * hv0.x + e01.y * hv0.y + e11.x * hv1.x + e11.y * hv1.y;
            dhp0 += acc[n0][0] * hv0.x + acc[n0][1] * hv0.y + acc[n1][0] * hv1.x + acc[n1][1] * hv1.y;
            dhp1 += acc[n0][2] * hv0.x + acc[n0][3] * hv0.y + acc[n1][2] * hv1.x + acc[n1][3] * hv1.y;
        }
#pragma unroll
        for (int s = 1; s < 4; s <<= 1) {
            c1p0 += __shfl_xor_sync(0xffffffffu, c1p0, s);
            c1p1 += __shfl_xor_sync(0xffffffffu, c1p1, s);
            c2p0 += __shfl_xor_sync(0xffffffffu, c2p0, s);
            c2p1 += __shfl_xor_sync(0xffffffffu, c2p1, s);
            drp0 += __shfl_xor_sync(0xffffffffu, drp0, s);
            drp1 += __shfl_xor_sync(0xffffffffu, drp1, s);
            dhp0 += __shfl_xor_sync(0xffffffffu, dhp0, s);
            dhp1 += __shfl_xor_sync(0xffffffffu, dhp1, s);
        }
        if (tg == 0) {
            sc1[m0 + g] = c1p0; sc1[m0 + g + 8] = c1p1;
            sc2[m0 + g] = c2p0; sc2[m0 + g + 8] = c2p1;
            sdr[m0 + g] = drp0; sdr[m0 + g + 8] = drp1;
            sdh[m0 + g] = dhp0; sdh[m0 + g + 8] = dhp1;
        }
    }
    __syncthreads();

    // ---- layer 1: softmax (warp 0; s2 inline) ----
    if (t < 32) {
        float v = shs[t] * shs[t] + shs[t + 32] * shs[t + 32];
#pragma unroll
        for (int s = 16; s; s >>= 1) v += __shfl_xor_sync(0xffffffffu, v, s);
        const float s2 = v;
        float e[2];
#pragma unroll
        for (int h = 0; h < 2; h++) {
            int k = t + 32 * h;
            float num = sc1[k] + sdr[k];
            float hn2 = s2 + 2.0f * sdh[k] + sc2[k];
            float hn = sqrtf(fmaxf(hn2, 0.0f));
            float rn = sqrtf(sr2[k]);
            float den = fmaxf(hn, 1e-8f) * fmaxf(rn, 1e-8f);
            float ee = num / den;
            ee = (ee < 0.0f) ? 0.2f * ee : ee;
            e[h] = (smask[k] > 0) ? ee : -9e15f;
        }
        float m = fmaxf(e[0], e[1]);
#pragma unroll
        for (int s = 16; s; s >>= 1) m = fmaxf(m, __shfl_xor_sync(0xffffffffu, m, s));
        float x0 = __expf(e[0] - m), x1 = __expf(e[1] - m);
        float sum = x0 + x1;
#pragma unroll
        for (int s = 16; s; s >>= 1) sum += __shfl_xor_sync(0xffffffffu, sum, s);
        float inv = 1.0f / sum;
        satt[t] = x0 * inv; satt[t + 32] = x1 * inv;
    }
    __syncthreads();
    // ---- layer 1: agg + residual -> new src ----
    {
        float a0 = 0.f, a1 = 0.f;
#pragma unroll
        for (int j = 0; j < 16; j++) {
            const int k = 16 * w + j;
            const float av = satt[k];
            float2 dd = *(const float2*)(gdst + k * 64 + 2 * l);
            a0 = fmaf(av, dd.x, a0);
            a1 = fmaf(av, dd.y, a1);
        }
        *(float2*)&sagg[w * 64 + 2 * l] = make_float2(a0, a1);
    }
    __syncthreads();
    if (t < D)
        ssrc[t] = (sagg[t] + sagg[64 + t]) + (sagg[128 + t] + sagg[192 + t]) + ssrc[t];
    __syncthreads();

    // ===================== layer 2 (R9 structure) =====================
    // hs2 = W1 @ src + b
    {
        float acc[4] = {0.f, 0.f, 0.f, 0.f};
#pragma unroll
        for (int ks = 0; ks < 4; ks++) {
            const int k0 = ks * 16;
            float2 v0 = *(const float2*)&ssrc[k0 + 2 * tg];
            float2 v1 = *(const float2*)&ssrc[k0 + 2 * tg + 8];
            unsigned h0, lo0, h1, lo1;
            split2(v0, h0, lo0);
            split2(v1, h1, lo1);
            unsigned B0 = (g == 0) ? h0 : (g == 1) ? lo0 : 0u;
            unsigned B1 = (g == 0) ? h1 : (g == 1) ? lo1 : 0u;
            uint4 Ah = g_AW1hi[(w * 4 + ks) * 32 + l];
            uint4 Al = g_AW1lo[(w * 4 + ks) * 32 + l];
            MMA(acc, ((unsigned*)&Ah), B0, B1);
            MMA(acc, ((unsigned*)&Al), B0, B1);
        }
        if (tg == 0) {
            shs[m0 + g] = acc[0] + acc[1] + sb[m0 + g];
            shs[m0 + g + 8] = acc[2] + acc[3] + sb[m0 + g + 8];
        }
    }
    __syncthreads();
    // g2 = W2^T @ hs
    {
        float acc[4] = {0.f, 0.f, 0.f, 0.f};
#pragma unroll
        for (int ks = 0; ks < 4; ks++) {
            const int k0 = ks * 16;
            float2 v0 = *(const float2*)&shs[k0 + 2 * tg];
            float2 v1 = *(const float2*)&shs[k0 + 2 * tg + 8];
            unsigned h0, lo0, h1, lo1;
            split2(v0, h0, lo0);
            split2(v1, h1, lo1);
            unsigned B0 = (g == 0) ? h0 : (g == 1) ? lo0 : 0u;
            unsigned B1 = (g == 0) ? h1 : (g == 1) ? lo1 : 0u;
            uint4 Ah = g_AW2hi[(w * 4 + ks) * 32 + l];
            uint4 Al = g_AW2lo[(w * 4 + ks) * 32 + l];
            MMA(acc, ((unsigned*)&Ah), B0, B1);
            MMA(acc, ((unsigned*)&Al), B0, B1);
        }
        if (tg == 0) {
            sg[m0 + g] = acc[0] + acc[1];
            sg[m0 + g + 8] = acc[2] + acc[3];
        }
    }
    __syncthreads();
    // dots2 via MMA: B cols [hs_hi, hs_lo, g_hi, g_lo]; A = rel (dr), dst (dh)
    {
        const float* vecp = (g & 2) ? sg : shs;
        const unsigned isLo = g & 1;
        float accR[4] = {0.f, 0.f, 0.f, 0.f};
        float accD[4] = {0.f, 0.f, 0.f, 0.f};
#pragma unroll
        for (int ks = 0; ks < 4; ks++) {
            const int k0 = ks * 16;
            float2 v0 = *(const float2*)&vecp[k0 + 2 * tg];
            float2 v1 = *(const float2*)&vecp[k0 + 2 * tg + 8];
            unsigned h0, lo0, h1, lo1;
            split2(v0, h0, lo0);
            split2(v1, h1, lo1);
            unsigned B0 = isLo ? lo0 : h0;
            unsigned B1 = isLo ? lo1 : h1;
            if (g >= 4) { B0 = 0u; B1 = 0u; }
            unsigned F[4];
            ldmat4(F, aRhi + lmrow + ks * 32);
            MMA(accR, F, B0, B1);
            ldmat4(F, aRlo + lmrow + ks * 32);
            MMA(accR, F, B0, B1);
            ldmat4(F, aDhi + lmrow + ks * 32);
            MMA(accD, F, B0, B1);
            ldmat4(F, aDlo + lmrow + ks * 32);
            MMA(accD, F, B0, B1);
        }
        if (tg == 0) { sdr[m0 + g] = accR[0] + accR[1]; sdr[m0 + g + 8] = accR[2] + accR[3]; }
        if (tg == 1) { sdh[m0 + g] = accD[0] + accD[1]; sdh[m0 + g + 8] = accD[2] + accD[3]; }
    }
    __syncthreads();
    // softmax2 (warp 0)
    if (t < 32) {
        float v = shs[t] * shs[t] + shs[t + 32] * shs[t + 32];
#pragma unroll
        for (int s = 16; s; s >>= 1) v += __shfl_xor_sync(0xffffffffu, v, s);
        const float s2 = v;
        float e[2];
#pragma unroll
        for (int h = 0; h < 2; h++) {
            int k = t + 32 * h;
            float num = sc1[k] + sdr[k];
            float hn2 = s2 + 2.0f * sdh[k] + sc2[k];
            float hn = sqrtf(fmaxf(hn2, 0.0f));
            float rn = sqrtf(sr2[k]);
            float den = fmaxf(hn, 1e-8f) * fmaxf(rn, 1e-8f);
            float ee = num / den;
            ee = (ee < 0.0f) ? 0.2f * ee : ee;
            e[h] = (smask[k] > 0) ? ee : -9e15f;
        }
        float m = fmaxf(e[0], e[1]);
#pragma unroll
        for (int s = 16; s; s >>= 1) m = fmaxf(m, __shfl_xor_sync(0xffffffffu, m, s));
        float x0 = __expf(e[0] - m), x1 = __expf(e[1] - m);
        float sum = x0 + x1;
#pragma unroll
        for (int s = 16; s; s >>= 1) sum += __shfl_xor_sync(0xffffffffu, sum, s);
        float inv = 1.0f / sum;
        satt[t] = x0 * inv; satt[t + 32] = x1 * inv;
    }
    __syncthreads();
    // agg2 + residual -> out
    {
        float a0 = 0.f, a1 = 0.f;
#pragma unroll
        for (int j = 0; j < 16; j++) {
            const int k = 16 * w + j;
            const float av = satt[k];
            float2 dd = *(const float2*)(gdst + k * 64 + 2 * l);
            a0 = fmaf(av, dd.x, a0);
            a1 = fmaf(av, dd.y, a1);
        }
        *(float2*)&sagg[w * 64 + 2 * l] = make_float2(a0, a1);
    }
    __syncthreads();
    if (t < D)
        out[(size_t)n * D + t] =
            (sagg[t] + sagg[64 + t]) + (sagg[128 + t] + sagg[192 + t]) + ssrc[t];
}

extern "C" void kernel_launch(void* const* d_in, const int* in_sizes, int n_in,
                              void* d_out, int out_size) {
    const float* src  = (const float*)d_in[0];
    const float* dst  = (const float*)d_in[1];
    const float* rel  = (const float*)d_in[2];
    const float* fcw  = (const float*)d_in[3];
    const float* fcb  = (const float*)d_in[4];
    const int*   mask = (const int*)d_in[5];
    (void)n_in;

    int N = in_sizes[0] / D;   // 50000
    float* outp = (float*)d_out;
    (void)out_size;

    prep_kernel<<<8, 256>>>(fcw);
    kgat_kernel<<<N, 128>>>(src, dst, rel, fcb, mask, outp);
}

// round 14
// speedup vs baseline: 1.2907x; 1.0397x over previous
#include <cuda_runtime.h>
#include <cuda_bf16.h>
#include <cstdint>

#define D 64
#define KNB 64
#define PADB 72    // bf16 smem row stride in shorts (144B): ldmatrix conflict-free

// ---------------- packed weights in global (prep once) ----------------
__device__ __align__(16) uint4 g_BW2[1024];   // GEMM B frags, lane-consecutive: [(nt*4+ks)*32 + l]
__device__ __align__(16) uint4 g_AW1hi[512];  // hs matvec A frags: [(mi*4+ks)*32+l]
__device__ __align__(16) uint4 g_AW1lo[512];

#define MMA(ac, A, B0, B1) \
    asm volatile("mma.sync.aligned.m16n8k16.row.col.f32.bf16.bf16.f32 " \
        "{%0,%1,%2,%3}, {%4,%5,%6,%7}, {%8,%9}, {%0,%1,%2,%3};" \
        : "+f"((ac)[0]), "+f"((ac)[1]), "+f"((ac)[2]), "+f"((ac)[3]) \
        : "r"((A)[0]), "r"((A)[1]), "r"((A)[2]), "r"((A)[3]), "r"(B0), "r"(B1))

__device__ __forceinline__ uint32_t smem_u32(const void* p) {
    uint32_t a;
    asm("{ .reg .u64 t; cvta.to.shared.u64 t, %1; cvt.u32.u64 %0, t; }" : "=r"(a) : "l"(p));
    return a;
}
__device__ __forceinline__ void ldmat4(unsigned r[4], uint32_t addr) {
    asm volatile("ldmatrix.sync.aligned.m8n8.x4.shared.b16 {%0,%1,%2,%3}, [%4];"
        : "=r"(r[0]), "=r"(r[1]), "=r"(r[2]), "=r"(r[3]) : "r"(addr));
}
__device__ __forceinline__ void split2(float2 f, unsigned& hi, unsigned& lo) {
    unsigned u0 = __float_as_uint(f.x), u1 = __float_as_uint(f.y);
    hi = (u0 >> 16) | (u1 & 0xFFFF0000u);
    float l0 = f.x - __uint_as_float(u0 & 0xFFFF0000u);
    float l1 = f.y - __uint_as_float(u1 & 0xFFFF0000u);
    __nv_bfloat162 p = __floats2bfloat162_rn(l0, l1);
    lo = *reinterpret_cast<unsigned*>(&p);
}
__device__ __forceinline__ float2 bfrecon(unsigned h, unsigned lo) {
    float2 a = __bfloat1622float2(*reinterpret_cast<__nv_bfloat162*>(&h));
    float2 b = __bfloat1622float2(*reinterpret_cast<__nv_bfloat162*>(&lo));
    return make_float2(a.x + b.x, a.y + b.y);
}
__device__ __forceinline__ float dot4(const float4& a, const float4& b) {
    return a.x * b.x + a.y * b.y + a.z * b.z + a.w * b.w;
}

// ---------------- prep kernel ----------------
__global__ void prep_kernel(const float* __restrict__ fc_w) {
    int idx = blockIdx.x * 256 + threadIdx.x;
    if (idx < 1024) {
        int nt = idx >> 7, ks = (idx >> 5) & 3, g = (idx >> 2) & 7, tg = idx & 3;
        int nn = nt * 8 + g;
        int c0 = ks * 16 + 2 * tg, c1 = c0 + 8;
        const float* Wn = fc_w + nn * 128 + 64;
        unsigned hx, lx, hy, ly;
        split2(make_float2(Wn[c0], Wn[c0 + 1]), hx, lx);
        split2(make_float2(Wn[c1], Wn[c1 + 1]), hy, ly);
        g_BW2[idx] = make_uint4(hx, hy, lx, ly);
    } else if (idx < 1536) {
        int jj = idx - 1024;
        int mi = jj >> 7, ks = (jj >> 5) & 3, l = jj & 31;
        int g = l >> 2, tg = l & 3;
        int ra = mi * 16 + g, rb = ra + 8;
        int c0 = ks * 16 + 2 * tg, c1 = c0 + 8;
        uint4 hi, lo;
        split2(make_float2(fc_w[ra * 128 + c0], fc_w[ra * 128 + c0 + 1]), hi.x, lo.x);
        split2(make_float2(fc_w[rb * 128 + c0], fc_w[rb * 128 + c0 + 1]), hi.y, lo.y);
        split2(make_float2(fc_w[ra * 128 + c1], fc_w[ra * 128 + c1 + 1]), hi.z, lo.z);
        split2(make_float2(fc_w[rb * 128 + c1], fc_w[rb * 128 + c1 + 1]), hi.w, lo.w);
        g_AW1hi[jj] = hi; g_AW1lo[jj] = lo;
    }
}

// ---------------- main fused kernel: 128 threads, 4 warps ----------------
__global__ void __launch_bounds__(128, 5) kgat_kernel(
    const float* __restrict__ src_embs,
    const float* __restrict__ dst_embs,
    const float* __restrict__ rel_embs,
    const float* __restrict__ fc_b,
    const int*   __restrict__ mask,
    float* __restrict__ out)
{
    __shared__ __align__(16) unsigned short sDhi[D * PADB];   // dst hi, later hd hi
    __shared__ __align__(16) unsigned short sDlo[D * PADB];   // dst lo, later hd lo
    __shared__ __align__(16) unsigned short sRhi[D * PADB];
    __shared__ __align__(16) unsigned short sRlo[D * PADB];
    __shared__ __align__(16) float ssrc[D], shs[D], sb[D];
    __shared__ float sc1[KNB], sc2[KNB], sr2[KNB];
    __shared__ float sdr[KNB], sdh[KNB], satt[KNB];
    __shared__ float sagg[4 * D];
    __shared__ int   smask[KNB];

    const int n = blockIdx.x;
    const int t = threadIdx.x;
    const int w = t >> 5, l = t & 31;
    const int g = l >> 2, tg = l & 3;

    const float* gdst = dst_embs + (size_t)n * (KNB * D);
    const float* grel = rel_embs + (size_t)n * (KNB * D);

    if (t < D) {
        ssrc[t] = src_embs[(size_t)n * D + t];
        sb[t] = fc_b[t];
        smask[t] = mask[(size_t)n * KNB + t];
    }

    // ---- prologue: split dst/rel into bf16 hi/lo smem; fold in r2 ----
    {
        const float4* gd4 = (const float4*)gdst;
        const float4* gr4 = (const float4*)grel;
#pragma unroll
        for (int j = 0; j < 8; j++) {
            int i = t + 128 * j;
            int row = i >> 4, c4 = i & 15;
            float4 dv = gd4[i];
            unsigned h0, l0, h1, l1;
            split2(make_float2(dv.x, dv.y), h0, l0);
            split2(make_float2(dv.z, dv.w), h1, l1);
            *(uint2*)&sDhi[row * PADB + c4 * 4] = make_uint2(h0, h1);
            *(uint2*)&sDlo[row * PADB + c4 * 4] = make_uint2(l0, l1);
            float4 rv = gr4[i];
            split2(make_float2(rv.x, rv.y), h0, l0);
            split2(make_float2(rv.z, rv.w), h1, l1);
            *(uint2*)&sRhi[row * PADB + c4 * 4] = make_uint2(h0, h1);
            *(uint2*)&sRlo[row * PADB + c4 * 4] = make_uint2(l0, l1);
            float r2p = dot4(rv, rv);
            r2p += __shfl_xor_sync(0xffffffffu, r2p, 1);
            r2p += __shfl_xor_sync(0xffffffffu, r2p, 2);
            r2p += __shfl_xor_sync(0xffffffffu, r2p, 4);
            r2p += __shfl_xor_sync(0xffffffffu, r2p, 8);
            if ((l & 15) == 0) sr2[row] = r2p;
        }
    }
    __syncthreads();

    const uint32_t aDhi = smem_u32(sDhi), aDlo = smem_u32(sDlo);
    const uint32_t aRhi = smem_u32(sRhi), aRlo = smem_u32(sRlo);
    const int m0 = w * 16;
    const uint32_t lmrow = (uint32_t)(m0 + (l & 15)) * (PADB * 2) + (uint32_t)(l >> 4) * 16;

    // ---- hs1 = W1 @ src + b via MMA ----
    {
        float acc[4] = {0.f, 0.f, 0.f, 0.f};
#pragma unroll
        for (int ks = 0; ks < 4; ks++) {
            const int k0 = ks * 16;
            float2 v0 = *(const float2*)&ssrc[k0 + 2 * tg];
            float2 v1 = *(const float2*)&ssrc[k0 + 2 * tg + 8];
            unsigned h0, lo0, h1, lo1;
            split2(v0, h0, lo0);
            split2(v1, h1, lo1);
            unsigned B0 = (g == 0) ? h0 : (g == 1) ? lo0 : 0u;
            unsigned B1 = (g == 0) ? h1 : (g == 1) ? lo1 : 0u;
            uint4 Ah = g_AW1hi[(w * 4 + ks) * 32 + l];
            uint4 Al = g_AW1lo[(w * 4 + ks) * 32 + l];
            MMA(acc, ((unsigned*)&Ah), B0, B1);
            MMA(acc, ((unsigned*)&Al), B0, B1);
        }
        if (tg == 0) {
            shs[m0 + g] = acc[0] + acc[1] + sb[m0 + g];
            shs[m0 + g + 8] = acc[2] + acc[3] + sb[m0 + g + 8];
        }
    }
    __syncthreads();

    // ==== GEMM: hd = dst @ W2^T; epilogue: c1, c2, dr1, dh1 + store hd over dst smem ====
    {
        float acc[8][4];
#pragma unroll
        for (int i = 0; i < 8; i++)
#pragma unroll
            for (int j = 0; j < 4; j++) acc[i][j] = 0.f;

#pragma unroll
        for (int ks = 0; ks < 4; ks++) {
            unsigned Ahi[4], Alo[4];
            ldmat4(Ahi, aDhi + lmrow + ks * 32);
            ldmat4(Alo, aDlo + lmrow + ks * 32);
#pragma unroll
            for (int nt = 0; nt < 8; nt++) {
                uint4 Bc = g_BW2[((nt * 4 + ks) << 5) + l];
                MMA(acc[nt], Ahi, Bc.x, Bc.y);
                MMA(acc[nt], Alo, Bc.x, Bc.y);
                MMA(acc[nt], Ahi, Bc.z, Bc.w);
            }
        }
        float c1p0 = 0.f, c1p1 = 0.f, c2p0 = 0.f, c2p1 = 0.f;
        float drp0 = 0.f, drp1 = 0.f, dhp0 = 0.f, dhp1 = 0.f;
#pragma unroll
        for (int cc = 0; cc < 4; cc++) {
            unsigned Rh[4], Rl[4];
            ldmat4(Rh, aRhi + lmrow + cc * 32);
            ldmat4(Rl, aRlo + lmrow + cc * 32);
            float2 e00 = bfrecon(Rh[0], Rl[0]);
            float2 e01 = bfrecon(Rh[1], Rl[1]);
            float2 e10 = bfrecon(Rh[2], Rl[2]);
            float2 e11 = bfrecon(Rh[3], Rl[3]);
            const int n0 = 2 * cc, n1 = 2 * cc + 1;
            float2 hv0 = *(const float2*)&shs[n0 * 8 + 2 * tg];
            float2 hv1 = *(const float2*)&shs[n1 * 8 + 2 * tg];
            c1p0 += acc[n0][0] * e00.x + acc[n0][1] * e00.y + acc[n1][0] * e10.x + acc[n1][1] * e10.y;
            c1p1 += acc[n0][2] * e01.x + acc[n0][3] * e01.y + acc[n1][2] * e11.x + acc[n1][3] * e11.y;
            c2p0 += acc[n0][0] * acc[n0][0] + acc[n0][1] * acc[n0][1] + acc[n1][0] * acc[n1][0] + acc[n1][1] * acc[n1][1];
            c2p1 += acc[n0][2] * acc[n0][2] + acc[n0][3] * acc[n0][3] + acc[n1][2] * acc[n1][2] + acc[n1][3] * acc[n1][3];
            drp0 += e00.x * hv0.x + e00.y * hv0.y + e10.x * hv1.x + e10.y * hv1.y;
            drp1 += e01.x * hv0.x + e01.y * hv0.y + e11.x * hv1.x + e11.y * hv1.y;
            dhp0 += acc[n0][0] * hv0.x + acc[n0][1] * hv0.y + acc[n1][0] * hv1.x + acc[n1][1] * hv1.y;
            dhp1 += acc[n0][2] * hv0.x + acc[n0][3] * hv0.y + acc[n1][2] * hv1.x + acc[n1][3] * hv1.y;
        }
        // store hd (bf16 hi/lo) over dst smem — warp-local rows, conflict-free STS.32
#pragma unroll
        for (int nt = 0; nt < 8; nt++) {
            unsigned hh, ll;
            split2(make_float2(acc[nt][0], acc[nt][1]), hh, ll);
            *(unsigned*)&sDhi[(m0 + g) * PADB + nt * 8 + 2 * tg] = hh;
            *(unsigned*)&sDlo[(m0 + g) * PADB + nt * 8 + 2 * tg] = ll;
            split2(make_float2(acc[nt][2], acc[nt][3]), hh, ll);
            *(unsigned*)&sDhi[(m0 + g + 8) * PADB + nt * 8 + 2 * tg] = hh;
            *(unsigned*)&sDlo[(m0 + g + 8) * PADB + nt * 8 + 2 * tg] = ll;
        }
#pragma unroll
        for (int s = 1; s < 4; s <<= 1) {
            c1p0 += __shfl_xor_sync(0xffffffffu, c1p0, s);
            c1p1 += __shfl_xor_sync(0xffffffffu, c1p1, s);
            c2p0 += __shfl_xor_sync(0xffffffffu, c2p0, s);
            c2p1 += __shfl_xor_sync(0xffffffffu, c2p1, s);
            drp0 += __shfl_xor_sync(0xffffffffu, drp0, s);
            drp1 += __shfl_xor_sync(0xffffffffu, drp1, s);
            dhp0 += __shfl_xor_sync(0xffffffffu, dhp0, s);
            dhp1 += __shfl_xor_sync(0xffffffffu, dhp1, s);
        }
        if (tg == 0) {
            sc1[m0 + g] = c1p0; sc1[m0 + g + 8] = c1p1;
            sc2[m0 + g] = c2p0; sc2[m0 + g + 8] = c2p1;
            sdr[m0 + g] = drp0; sdr[m0 + g + 8] = drp1;
            sdh[m0 + g] = dhp0; sdh[m0 + g + 8] = dhp1;
        }
    }
    __syncthreads();

    // ---- layer 1: softmax (warp 0; s2 inline) ----
    if (t < 32) {
        float v = shs[t] * shs[t] + shs[t + 32] * shs[t + 32];
#pragma unroll
        for (int s = 16; s; s >>= 1) v += __shfl_xor_sync(0xffffffffu, v, s);
        const float s2 = v;
        float e[2];
#pragma unroll
        for (int h = 0; h < 2; h++) {
            int k = t + 32 * h;
            float num = sc1[k] + sdr[k];
            float hn2 = s2 + 2.0f * sdh[k] + sc2[k];
            float hn = sqrtf(fmaxf(hn2, 0.0f));
            float rn = sqrtf(sr2[k]);
            float den = fmaxf(hn, 1e-8f) * fmaxf(rn, 1e-8f);
            float ee = num / den;
            ee = (ee < 0.0f) ? 0.2f * ee : ee;
            e[h] = (smask[k] > 0) ? ee : -9e15f;
        }
        float m = fmaxf(e[0], e[1]);
#pragma unroll
        for (int s = 16; s; s >>= 1) m = fmaxf(m, __shfl_xor_sync(0xffffffffu, m, s));
        float x0 = __expf(e[0] - m), x1 = __expf(e[1] - m);
        float sum = x0 + x1;
#pragma unroll
        for (int s = 16; s; s >>= 1) sum += __shfl_xor_sync(0xffffffffu, sum, s);
        float inv = 1.0f / sum;
        satt[t] = x0 * inv; satt[t + 32] = x1 * inv;
    }
    __syncthreads();
    // ---- layer 1: agg + residual -> new src ----
    {
        float a0 = 0.f, a1 = 0.f;
#pragma unroll
        for (int j = 0; j < 16; j++) {
            const int k = 16 * w + j;
            const float av = satt[k];
            float2 dd = *(const float2*)(gdst + k * 64 + 2 * l);
            a0 = fmaf(av, dd.x, a0);
            a1 = fmaf(av, dd.y, a1);
        }
        *(float2*)&sagg[w * 64 + 2 * l] = make_float2(a0, a1);
    }
    __syncthreads();
    if (t < D)
        ssrc[t] = (sagg[t] + sagg[64 + t]) + (sagg[128 + t] + sagg[192 + t]) + ssrc[t];
    __syncthreads();

    // ===================== layer 2 =====================
    // hs2 = W1 @ src + b
    {
        float acc[4] = {0.f, 0.f, 0.f, 0.f};
#pragma unroll
        for (int ks = 0; ks < 4; ks++) {
            const int k0 = ks * 16;
            float2 v0 = *(const float2*)&ssrc[k0 + 2 * tg];
            float2 v1 = *(const float2*)&ssrc[k0 + 2 * tg + 8];
            unsigned h0, lo0, h1, lo1;
            split2(v0, h0, lo0);
            split2(v1, h1, lo1);
            unsigned B0 = (g == 0) ? h0 : (g == 1) ? lo0 : 0u;
            unsigned B1 = (g == 0) ? h1 : (g == 1) ? lo1 : 0u;
            uint4 Ah = g_AW1hi[(w * 4 + ks) * 32 + l];
            uint4 Al = g_AW1lo[(w * 4 + ks) * 32 + l];
            MMA(acc, ((unsigned*)&Ah), B0, B1);
            MMA(acc, ((unsigned*)&Al), B0, B1);
        }
        if (tg == 0) {
            shs[m0 + g] = acc[0] + acc[1] + sb[m0 + g];
            shs[m0 + g + 8] = acc[2] + acc[3] + sb[m0 + g + 8];
        }
    }
    __syncthreads();
    // dots2 via MMA: B = [hs_hi, hs_lo]; dr2: A = rel; dh2: A = hd (stored in sDhi/sDlo)
    {
        const unsigned isLo = g & 1;
        float accR[4] = {0.f, 0.f, 0.f, 0.f};
        float accD[4] = {0.f, 0.f, 0.f, 0.f};
#pragma unroll
        for (int ks = 0; ks < 4; ks++) {
            const int k0 = ks * 16;
            float2 v0 = *(const float2*)&shs[k0 + 2 * tg];
            float2 v1 = *(const float2*)&shs[k0 + 2 * tg + 8];
            unsigned h0, lo0, h1, lo1;
            split2(v0, h0, lo0);
            split2(v1, h1, lo1);
            unsigned B0 = isLo ? lo0 : h0;
            unsigned B1 = isLo ? lo1 : h1;
            if (g >= 2) { B0 = 0u; B1 = 0u; }
            unsigned F[4];
            ldmat4(F, aRhi + lmrow + ks * 32);
            MMA(accR, F, B0, B1);
            ldmat4(F, aRlo + lmrow + ks * 32);
            MMA(accR, F, B0, B1);
            ldmat4(F, aDhi + lmrow + ks * 32);
            MMA(accD, F, B0, B1);
            ldmat4(F, aDlo + lmrow + ks * 32);
            MMA(accD, F, B0, B1);
        }
        if (tg == 0) {
            sdr[m0 + g] = accR[0] + accR[1]; sdr[m0 + g + 8] = accR[2] + accR[3];
            sdh[m0 + g] = accD[0] + accD[1]; sdh[m0 + g + 8] = accD[2] + accD[3];
        }
    }
    __syncthreads();
    // softmax2 (warp 0)
    if (t < 32) {
        float v = shs[t] * shs[t] + shs[t + 32] * shs[t + 32];
#pragma unroll
        for (int s = 16; s; s >>= 1) v += __shfl_xor_sync(0xffffffffu, v, s);
        const float s2 = v;
        float e[2];
#pragma unroll
        for (int h = 0; h < 2; h++) {
            int k = t + 32 * h;
            float num = sc1[k] + sdr[k];
            float hn2 = s2 + 2.0f * sdh[k] + sc2[k];
            float hn = sqrtf(fmaxf(hn2, 0.0f));
            float rn = sqrtf(sr2[k]);
            float den = fmaxf(hn, 1e-8f) * fmaxf(rn, 1e-8f);
            float ee = num / den;
            ee = (ee < 0.0f) ? 0.2f * ee : ee;
            e[h] = (smask[k] > 0) ? ee : -9e15f;
        }
        float m = fmaxf(e[0], e[1]);
#pragma unroll
        for (int s = 16; s; s >>= 1) m = fmaxf(m, __shfl_xor_sync(0xffffffffu, m, s));
        float x0 = __expf(e[0] - m), x1 = __expf(e[1] - m);
        float sum = x0 + x1;
#pragma unroll
        for (int s = 16; s; s >>= 1) sum += __shfl_xor_sync(0xffffffffu, sum, s);
        float inv = 1.0f / sum;
        satt[t] = x0 * inv; satt[t + 32] = x1 * inv;
    }
    __syncthreads();
    // agg2 + residual -> out
    {
        float a0 = 0.f, a1 = 0.f;
#pragma unroll
        for (int j = 0; j < 16; j++) {
            const int k = 16 * w + j;
            const float av = satt[k];
            float2 dd = *(const float2*)(gdst + k * 64 + 2 * l);
            a0 = fmaf(av, dd.x, a0);
            a1 = fmaf(av, dd.y, a1);
        }
        *(float2*)&sagg[w * 64 + 2 * l] = make_float2(a0, a1);
    }
    __syncthreads();
    if (t < D)
        out[(size_t)n * D + t] =
            (sagg[t] + sagg[64 + t]) + (sagg[128 + t] + sagg[192 + t]) + ssrc[t];
}

extern "C" void kernel_launch(void* const* d_in, const int* in_sizes, int n_in,
                              void* d_out, int out_size) {
    const float* src  = (const float*)d_in[0];
    const float* dst  = (const float*)d_in[1];
    const float* rel  = (const float*)d_in[2];
    const float* fcw  = (const float*)d_in[3];
    const float* fcb  = (const float*)d_in[4];
    const int*   mask = (const int*)d_in[5];
    (void)n_in;

    int N = in_sizes[0] / D;   // 50000
    float* outp = (float*)d_out;
    (void)out_size;

    prep_kernel<<<8, 256>>>(fcw);
    kgat_kernel<<<N, 128>>>(src, dst, rel, fcb, mask, outp);
}

// round 15
// speedup vs baseline: 1.3620x; 1.0552x over previous
#include <cuda_runtime.h>
#include <cuda_bf16.h>
#include <cstdint>

#define D 64
#define KNB 64
#define PADB 72    // bf16 smem row stride in shorts (144B): ldmatrix conflict-free

// ---------------- packed weights in global (prep once) ----------------
__device__ __align__(16) uint4 g_BW2[1024];   // GEMM B frags, lane-consecutive: [(nt*4+ks)*32 + l]
__device__ __align__(16) uint4 g_AW1hi[512];  // hs matvec A frags: [(mi*4+ks)*32+l]
__device__ __align__(16) uint4 g_AW1lo[512];

#define MMA(ac, A, B0, B1) \
    asm volatile("mma.sync.aligned.m16n8k16.row.col.f32.bf16.bf16.f32 " \
        "{%0,%1,%2,%3}, {%4,%5,%6,%7}, {%8,%9}, {%0,%1,%2,%3};" \
        : "+f"((ac)[0]), "+f"((ac)[1]), "+f"((ac)[2]), "+f"((ac)[3]) \
        : "r"((A)[0]), "r"((A)[1]), "r"((A)[2]), "r"((A)[3]), "r"(B0), "r"(B1))

__device__ __forceinline__ uint32_t smem_u32(const void* p) {
    uint32_t a;
    asm("{ .reg .u64 t; cvta.to.shared.u64 t, %1; cvt.u32.u64 %0, t; }" : "=r"(a) : "l"(p));
    return a;
}
__device__ __forceinline__ void ldmat4(unsigned r[4], uint32_t addr) {
    asm volatile("ldmatrix.sync.aligned.m8n8.x4.shared.b16 {%0,%1,%2,%3}, [%4];"
        : "=r"(r[0]), "=r"(r[1]), "=r"(r[2]), "=r"(r[3]) : "r"(addr));
}
__device__ __forceinline__ void split2(float2 f, unsigned& hi, unsigned& lo) {
    unsigned u0 = __float_as_uint(f.x), u1 = __float_as_uint(f.y);
    hi = (u0 >> 16) | (u1 & 0xFFFF0000u);
    float l0 = f.x - __uint_as_float(u0 & 0xFFFF0000u);
    float l1 = f.y - __uint_as_float(u1 & 0xFFFF0000u);
    __nv_bfloat162 p = __floats2bfloat162_rn(l0, l1);
    lo = *reinterpret_cast<unsigned*>(&p);
}
__device__ __forceinline__ float2 bfrecon(unsigned h, unsigned lo) {
    float2 a = __bfloat1622float2(*reinterpret_cast<__nv_bfloat162*>(&h));
    float2 b = __bfloat1622float2(*reinterpret_cast<__nv_bfloat162*>(&lo));
    return make_float2(a.x + b.x, a.y + b.y);
}

// ---------------- prep kernel ----------------
__global__ void prep_kernel(const float* __restrict__ fc_w) {
    int idx = blockIdx.x * 256 + threadIdx.x;
    if (idx < 1024) {
        int nt = idx >> 7, ks = (idx >> 5) & 3, g = (idx >> 2) & 7, tg = idx & 3;
        int nn = nt * 8 + g;
        int c0 = ks * 16 + 2 * tg, c1 = c0 + 8;
        const float* Wn = fc_w + nn * 128 + 64;
        unsigned hx, lx, hy, ly;
        split2(make_float2(Wn[c0], Wn[c0 + 1]), hx, lx);
        split2(make_float2(Wn[c1], Wn[c1 + 1]), hy, ly);
        g_BW2[idx] = make_uint4(hx, hy, lx, ly);
    } else if (idx < 1536) {
        int jj = idx - 1024;
        int mi = jj >> 7, ks = (jj >> 5) & 3, l = jj & 31;
        int g = l >> 2, tg = l & 3;
        int ra = mi * 16 + g, rb = ra + 8;
        int c0 = ks * 16 + 2 * tg, c1 = c0 + 8;
        uint4 hi, lo;
        split2(make_float2(fc_w[ra * 128 + c0], fc_w[ra * 128 + c0 + 1]), hi.x, lo.x);
        split2(make_float2(fc_w[rb * 128 + c0], fc_w[rb * 128 + c0 + 1]), hi.y, lo.y);
        split2(make_float2(fc_w[ra * 128 + c1], fc_w[ra * 128 + c1 + 1]), hi.z, lo.z);
        split2(make_float2(fc_w[rb * 128 + c1], fc_w[rb * 128 + c1 + 1]), hi.w, lo.w);
        g_AW1hi[jj] = hi; g_AW1lo[jj] = lo;
    }
}

// ---------------- main fused kernel: 128 threads, 4 warps ----------------
__global__ void __launch_bounds__(128, 5) kgat_kernel(
    const float* __restrict__ src_embs,
    const float* __restrict__ dst_embs,
    const float* __restrict__ rel_embs,
    const float* __restrict__ fc_b,
    const int*   __restrict__ mask,
    float* __restrict__ out)
{
    __shared__ __align__(16) unsigned short sDhi[D * PADB];   // dst hi, later hd hi
    __shared__ __align__(16) unsigned short sDlo[D * PADB];   // dst lo, later hd lo
    __shared__ __align__(16) unsigned short sRhi[D * PADB];
    __shared__ __align__(16) unsigned short sRlo[D * PADB];
    __shared__ __align__(16) float ssrc[D], shs[D];
    __shared__ float sc1[KNB], sc2[KNB], sr2[KNB];
    __shared__ float sdr[KNB], sdh[KNB], satt[KNB];
    __shared__ float sagg[4 * D];
    __shared__ int   smask[KNB];

    const int n = blockIdx.x;
    const int t = threadIdx.x;
    const int w = t >> 5, l = t & 31;
    const int g = l >> 2, tg = l & 3;

    const float* gdst = dst_embs + (size_t)n * (KNB * D);
    const float* grel = rel_embs + (size_t)n * (KNB * D);
    const float* gsrc = src_embs + (size_t)n * D;

    const int m0 = w * 16;

    if (t < D) {
        ssrc[t] = gsrc[t];
        smask[t] = mask[(size_t)n * KNB + t];
    }

    // ---- prologue: split dst/rel into bf16 hi/lo smem (no r2, no shfl) ----
    {
        const float4* gd4 = (const float4*)gdst;
        const float4* gr4 = (const float4*)grel;
#pragma unroll
        for (int j = 0; j < 8; j++) {
            int i = t + 128 * j;
            int row = i >> 4, c4 = i & 15;
            float4 dv = gd4[i];
            unsigned h0, l0, h1, l1;
            split2(make_float2(dv.x, dv.y), h0, l0);
            split2(make_float2(dv.z, dv.w), h1, l1);
            *(uint2*)&sDhi[row * PADB + c4 * 4] = make_uint2(h0, h1);
            *(uint2*)&sDlo[row * PADB + c4 * 4] = make_uint2(l0, l1);
            float4 rv = gr4[i];
            split2(make_float2(rv.x, rv.y), h0, l0);
            split2(make_float2(rv.z, rv.w), h1, l1);
            *(uint2*)&sRhi[row * PADB + c4 * 4] = make_uint2(h0, h1);
            *(uint2*)&sRlo[row * PADB + c4 * 4] = make_uint2(l0, l1);
        }
    }

    // ---- hs1 = W1 @ src + b via MMA (src/bias from GLOBAL: overlaps prologue, no barrier) ----
    {
        float acc[4] = {0.f, 0.f, 0.f, 0.f};
#pragma unroll
        for (int ks = 0; ks < 4; ks++) {
            const int k0 = ks * 16;
            float2 v0 = *(const float2*)(gsrc + k0 + 2 * tg);
            float2 v1 = *(const float2*)(gsrc + k0 + 2 * tg + 8);
            unsigned h0, lo0, h1, lo1;
            split2(v0, h0, lo0);
            split2(v1, h1, lo1);
            unsigned B0 = (g == 0) ? h0 : (g == 1) ? lo0 : 0u;
            unsigned B1 = (g == 0) ? h1 : (g == 1) ? lo1 : 0u;
            uint4 Ah = g_AW1hi[(w * 4 + ks) * 32 + l];
            uint4 Al = g_AW1lo[(w * 4 + ks) * 32 + l];
            MMA(acc, ((unsigned*)&Ah), B0, B1);
            MMA(acc, ((unsigned*)&Al), B0, B1);
        }
        if (tg == 0) {
            shs[m0 + g] = acc[0] + acc[1] + fc_b[m0 + g];
            shs[m0 + g + 8] = acc[2] + acc[3] + fc_b[m0 + g + 8];
        }
    }
    __syncthreads();

    const uint32_t aDhi = smem_u32(sDhi), aDlo = smem_u32(sDlo);
    const uint32_t aRhi = smem_u32(sRhi), aRlo = smem_u32(sRlo);
    const uint32_t lmrow = (uint32_t)(m0 + (l & 15)) * (PADB * 2) + (uint32_t)(l >> 4) * 16;

    // ==== GEMM: hd = dst @ W2^T; epilogue: c1, c2, r2, dr1, dh1 + store hd over dst smem ====
    {
        float acc[8][4];
#pragma unroll
        for (int i = 0; i < 8; i++)
#pragma unroll
            for (int j = 0; j < 4; j++) acc[i][j] = 0.f;

#pragma unroll
        for (int ks = 0; ks < 4; ks++) {
            unsigned Ahi[4], Alo[4];
            ldmat4(Ahi, aDhi + lmrow + ks * 32);
            ldmat4(Alo, aDlo + lmrow + ks * 32);
#pragma unroll
            for (int nt = 0; nt < 8; nt++) {
                uint4 Bc = g_BW2[((nt * 4 + ks) << 5) + l];
                MMA(acc[nt], Ahi, Bc.x, Bc.y);
                MMA(acc[nt], Alo, Bc.x, Bc.y);
                MMA(acc[nt], Ahi, Bc.z, Bc.w);
            }
        }
        float c1p0 = 0.f, c1p1 = 0.f, c2p0 = 0.f, c2p1 = 0.f;
        float drp0 = 0.f, drp1 = 0.f, dhp0 = 0.f, dhp1 = 0.f;
        float r2p0 = 0.f, r2p1 = 0.f;
#pragma unroll
        for (int cc = 0; cc < 4; cc++) {
            unsigned Rh[4], Rl[4];
            ldmat4(Rh, aRhi + lmrow + cc * 32);
            ldmat4(Rl, aRlo + lmrow + cc * 32);
            float2 e00 = bfrecon(Rh[0], Rl[0]);
            float2 e01 = bfrecon(Rh[1], Rl[1]);
            float2 e10 = bfrecon(Rh[2], Rl[2]);
            float2 e11 = bfrecon(Rh[3], Rl[3]);
            const int n0 = 2 * cc, n1 = 2 * cc + 1;
            float2 hv0 = *(const float2*)&shs[n0 * 8 + 2 * tg];
            float2 hv1 = *(const float2*)&shs[n1 * 8 + 2 * tg];
            c1p0 += acc[n0][0] * e00.x + acc[n0][1] * e00.y + acc[n1][0] * e10.x + acc[n1][1] * e10.y;
            c1p1 += acc[n0][2] * e01.x + acc[n0][3] * e01.y + acc[n1][2] * e11.x + acc[n1][3] * e11.y;
            c2p0 += acc[n0][0] * acc[n0][0] + acc[n0][1] * acc[n0][1] + acc[n1][0] * acc[n1][0] + acc[n1][1] * acc[n1][1];
            c2p1 += acc[n0][2] * acc[n0][2] + acc[n0][3] * acc[n0][3] + acc[n1][2] * acc[n1][2] + acc[n1][3] * acc[n1][3];
            r2p0 += e00.x * e00.x + e00.y * e00.y + e10.x * e10.x + e10.y * e10.y;
            r2p1 += e01.x * e01.x + e01.y * e01.y + e11.x * e11.x + e11.y * e11.y;
            drp0 += e00.x * hv0.x + e00.y * hv0.y + e10.x * hv1.x + e10.y * hv1.y;
            drp1 += e01.x * hv0.x + e01.y * hv0.y + e11.x * hv1.x + e11.y * hv1.y;
            dhp0 += acc[n0][0] * hv0.x + acc[n0][1] * hv0.y + acc[n1][0] * hv1.x + acc[n1][1] * hv1.y;
            dhp1 += acc[n0][2] * hv0.x + acc[n0][3] * hv0.y + acc[n1][2] * hv1.x + acc[n1][3] * hv1.y;
        }
        // store hd (bf16 hi/lo) over dst smem — warp-local rows, conflict-free STS.32
#pragma unroll
        for (int nt = 0; nt < 8; nt++) {
            unsigned hh, ll;
            split2(make_float2(acc[nt][0], acc[nt][1]), hh, ll);
            *(unsigned*)&sDhi[(m0 + g) * PADB + nt * 8 + 2 * tg] = hh;
            *(unsigned*)&sDlo[(m0 + g) * PADB + nt * 8 + 2 * tg] = ll;
            split2(make_float2(acc[nt][2], acc[nt][3]), hh, ll);
            *(unsigned*)&sDhi[(m0 + g + 8) * PADB + nt * 8 + 2 * tg] = hh;
            *(unsigned*)&sDlo[(m0 + g + 8) * PADB + nt * 8 + 2 * tg] = ll;
        }
#pragma unroll
        for (int s = 1; s < 4; s <<= 1) {
            c1p0 += __shfl_xor_sync(0xffffffffu, c1p0, s);
            c1p1 += __shfl_xor_sync(0xffffffffu, c1p1, s);
            c2p0 += __shfl_xor_sync(0xffffffffu, c2p0, s);
            c2p1 += __shfl_xor_sync(0xffffffffu, c2p1, s);
            r2p0 += __shfl_xor_sync(0xffffffffu, r2p0, s);
            r2p1 += __shfl_xor_sync(0xffffffffu, r2p1, s);
            drp0 += __shfl_xor_sync(0xffffffffu, drp0, s);
            drp1 += __shfl_xor_sync(0xffffffffu, drp1, s);
            dhp0 += __shfl_xor_sync(0xffffffffu, dhp0, s);
            dhp1 += __shfl_xor_sync(0xffffffffu, dhp1, s);
        }
        if (tg == 0) {
            sc1[m0 + g] = c1p0; sc1[m0 + g + 8] = c1p1;
            sc2[m0 + g] = c2p0; sc2[m0 + g + 8] = c2p1;
            sr2[m0 + g] = r2p0; sr2[m0 + g + 8] = r2p1;
            sdr[m0 + g] = drp0; sdr[m0 + g + 8] = drp1;
            sdh[m0 + g] = dhp0; sdh[m0 + g + 8] = dhp1;
        }
    }
    __syncthreads();

    // ---- layer 1: softmax (warp 0; s2 inline) ----
    if (t < 32) {
        float v = shs[t] * shs[t] + shs[t + 32] * shs[t + 32];
#pragma unroll
        for (int s = 16; s; s >>= 1) v += __shfl_xor_sync(0xffffffffu, v, s);
        const float s2 = v;
        float e[2];
#pragma unroll
        for (int h = 0; h < 2; h++) {
            int k = t + 32 * h;
            float num = sc1[k] + sdr[k];
            float hn2 = s2 + 2.0f * sdh[k] + sc2[k];
            float hn = sqrtf(fmaxf(hn2, 0.0f));
            float rn = sqrtf(sr2[k]);
            float den = fmaxf(hn, 1e-8f) * fmaxf(rn, 1e-8f);
            float ee = num / den;
            ee = (ee < 0.0f) ? 0.2f * ee : ee;
            e[h] = (smask[k] > 0) ? ee : -9e15f;
        }
        float m = fmaxf(e[0], e[1]);
#pragma unroll
        for (int s = 16; s; s >>= 1) m = fmaxf(m, __shfl_xor_sync(0xffffffffu, m, s));
        float x0 = __expf(e[0] - m), x1 = __expf(e[1] - m);
        float sum = x0 + x1;
#pragma unroll
        for (int s = 16; s; s >>= 1) sum += __shfl_xor_sync(0xffffffffu, sum, s);
        float inv = 1.0f / sum;
        satt[t] = x0 * inv; satt[t + 32] = x1 * inv;
    }
    __syncthreads();
    // ---- layer 1: agg + residual -> new src ----
    {
        float a0 = 0.f, a1 = 0.f;
#pragma unroll
        for (int j = 0; j < 16; j++) {
            const int k = 16 * w + j;
            const float av = satt[k];
            float2 dd = *(const float2*)(gdst + k * 64 + 2 * l);
            a0 = fmaf(av, dd.x, a0);
            a1 = fmaf(av, dd.y, a1);
        }
        *(float2*)&sagg[w * 64 + 2 * l] = make_float2(a0, a1);
    }
    __syncthreads();
    if (t < D)
        ssrc[t] = (sagg[t] + sagg[64 + t]) + (sagg[128 + t] + sagg[192 + t]) + ssrc[t];
    __syncthreads();

    // ===================== layer 2 =====================
    // hs2 = W1 @ src + b
    {
        float acc[4] = {0.f, 0.f, 0.f, 0.f};
#pragma unroll
        for (int ks = 0; ks < 4; ks++) {
            const int k0 = ks * 16;
            float2 v0 = *(const float2*)&ssrc[k0 + 2 * tg];
            float2 v1 = *(const float2*)&ssrc[k0 + 2 * tg + 8];
            unsigned h0, lo0, h1, lo1;
            split2(v0, h0, lo0);
            split2(v1, h1, lo1);
            unsigned B0 = (g == 0) ? h0 : (g == 1) ? lo0 : 0u;
            unsigned B1 = (g == 0) ? h1 : (g == 1) ? lo1 : 0u;
            uint4 Ah = g_AW1hi[(w * 4 + ks) * 32 + l];
            uint4 Al = g_AW1lo[(w * 4 + ks) * 32 + l];
            MMA(acc, ((unsigned*)&Ah), B0, B1);
            MMA(acc, ((unsigned*)&Al), B0, B1);
        }
        if (tg == 0) {
            shs[m0 + g] = acc[0] + acc[1] + fc_b[m0 + g];
            shs[m0 + g + 8] = acc[2] + acc[3] + fc_b[m0 + g + 8];
        }
    }
    __syncthreads();
    // dots2 via MMA: B = [hs_hi, hs_lo]; dr2: A = rel; dh2: A = hd (stored in sDhi/sDlo)
    {
        const unsigned isLo = g & 1;
        float accR[4] = {0.f, 0.f, 0.f, 0.f};
        float accD[4] = {0.f, 0.f, 0.f, 0.f};
#pragma unroll
        for (int ks = 0; ks < 4; ks++) {
            const int k0 = ks * 16;
            float2 v0 = *(const float2*)&shs[k0 + 2 * tg];
            float2 v1 = *(const float2*)&shs[k0 + 2 * tg + 8];
            unsigned h0, lo0, h1, lo1;
            split2(v0, h0, lo0);
            split2(v1, h1, lo1);
            unsigned B0 = isLo ? lo0 : h0;
            unsigned B1 = isLo ? lo1 : h1;
            if (g >= 2) { B0 = 0u; B1 = 0u; }
            unsigned F[4];
            ldmat4(F, aRhi + lmrow + ks * 32);
            MMA(accR, F, B0, B1);
            ldmat4(F, aRlo + lmrow + ks * 32);
            MMA(accR, F, B0, B1);
            ldmat4(F, aDhi + lmrow + ks * 32);
            MMA(accD, F, B0, B1);
            ldmat4(F, aDlo + lmrow + ks * 32);
            MMA(accD, F, B0, B1);
        }
        if (tg == 0) {
            sdr[m0 + g] = accR[0] + accR[1]; sdr[m0 + g + 8] = accR[2] + accR[3];
            sdh[m0 + g] = accD[0] + accD[1]; sdh[m0 + g + 8] = accD[2] + accD[3];
        }
    }
    __syncthreads();
    // softmax2 (warp 0)
    if (t < 32) {
        float v = shs[t] * shs[t] + shs[t + 32] * shs[t + 32];
#pragma unroll
        for (int s = 16; s; s >>= 1) v += __shfl_xor_sync(0xffffffffu, v, s);
        const float s2 = v;
        float e[2];
#pragma unroll
        for (int h = 0; h < 2; h++) {
            int k = t + 32 * h;
            float num = sc1[k] + sdr[k];
            float hn2 = s2 + 2.0f * sdh[k] + sc2[k];
            float hn = sqrtf(fmaxf(hn2, 0.0f));
            float rn = sqrtf(sr2[k]);
            float den = fmaxf(hn, 1e-8f) * fmaxf(rn, 1e-8f);
            float ee = num / den;
            ee = (ee < 0.0f) ? 0.2f * ee : ee;
            e[h] = (smask[k] > 0) ? ee : -9e15f;
        }
        float m = fmaxf(e[0], e[1]);
#pragma unroll
        for (int s = 16; s; s >>= 1) m = fmaxf(m, __shfl_xor_sync(0xffffffffu, m, s));
        float x0 = __expf(e[0] - m), x1 = __expf(e[1] - m);
        float sum = x0 + x1;
#pragma unroll
        for (int s = 16; s; s >>= 1) sum += __shfl_xor_sync(0xffffffffu, sum, s);
        float inv = 1.0f / sum;
        satt[t] = x0 * inv; satt[t + 32] = x1 * inv;
    }
    __syncthreads();
    // agg2 + residual -> out
    {
        float a0 = 0.f, a1 = 0.f;
#pragma unroll
        for (int j = 0; j < 16; j++) {
            const int k = 16 * w + j;
            const float av = satt[k];
            float2 dd = *(const float2*)(gdst + k * 64 + 2 * l);
            a0 = fmaf(av, dd.x, a0);
            a1 = fmaf(av, dd.y, a1);
        }
        *(float2*)&sagg[w * 64 + 2 * l] = make_float2(a0, a1);
    }
    __syncthreads();
    if (t < D)
        out[(size_t)n * D + t] =
            (sagg[t] + sagg[64 + t]) + (sagg[128 + t] + sagg[192 + t]) + ssrc[t];
}

extern "C" void kernel_launch(void* const* d_in, const int* in_sizes, int n_in,
                              void* d_out, int out_size) {
    const float* src  = (const float*)d_in[0];
    const float* dst  = (const float*)d_in[1];
    const float* rel  = (const float*)d_in[2];
    const float* fcw  = (const float*)d_in[3];
    const float* fcb  = (const float*)d_in[4];
    const int*   mask = (const int*)d_in[5];
    (void)n_in;

    int N = in_sizes[0] / D;   // 50000
    float* outp = (float*)d_out;
    (void)out_size;

    prep_kernel<<<8, 256>>>(fcw);
    kgat_kernel<<<N, 128>>>(src, dst, rel, fcb, mask, outp);
}